// round 1
// baseline (speedup 1.0000x reference)
#include <cuda_runtime.h>
#include <cuda_bf16.h>
#include <math.h>

// ---------------------------------------------------------------------------
// DeepseekV2 MLA forward, B=1 S=2048 HID=2048 H=16 NOPE=128 ROPE=64 VD=128
// QD=192 QLR=1536 KVLR=512. Outputs: out [1,2048,2048] fp32 then
// attn [1,16,2048,2048] fp32, concatenated in d_out.
// Pipeline (all fp32, matches reference numerics):
//   1. qraw = hid @ Wq_down^T + bq        (2048x1536)
//   2. rmsnorm(qraw, gq) in-place
//   3. q    = qraw @ Wq_up^T              (2048x3072)
//   4. kvd  = hid @ Wkv_down^T + bkv      (2048x576)
//   5. rmsnorm(kvd[:, :512], gkv) in-place (k_rope cols 512..575 untouched)
//   6. kv   = kvd[:, :512] @ Wkv_up^T     (2048x4096)
//   7. assemble+RoPE -> qall[h][s][192], kall[h][s][192], vt[h][128][2048]
//   8. scores (causal-skipped batched NT gemm) -> attn region, scaled
//   9. causal softmax rows (writes zeros above diagonal)
//  10. ctx = attn @ v (batched, K clamped to diagonal) -> ctx[s][h*128]
//  11. out = ctx @ Wo^T
// ---------------------------------------------------------------------------

#define S_LEN 2048
#define HID   2048
#define HEADS 16
#define NOPE  128
#define ROPE  64
#define VD    128
#define QD    192
#define QLR   1536
#define KVLR  512
#define KVD_W (KVLR + ROPE)   // 576
#define QUP_N (HEADS * QD)    // 3072
#define KUP_N (HEADS * (NOPE + VD)) // 4096

// scratch layout (floats)
#define OFF_QRAW 0L
#define OFF_Q    (OFF_QRAW + (long)S_LEN * QLR)          // 3,145,728
#define OFF_KVD  (OFF_Q    + (long)S_LEN * QUP_N)        // +6,291,456
#define OFF_KV   (OFF_KVD  + (long)S_LEN * KVD_W)        // +1,179,648
#define OFF_QALL (OFF_KV   + (long)S_LEN * KUP_N)        // +8,388,608
#define OFF_KALL (OFF_QALL + (long)HEADS * S_LEN * QD)   // +6,291,456
#define OFF_VT   (OFF_KALL + (long)HEADS * S_LEN * QD)   // +6,291,456
#define OFF_CTX  (OFF_VT   + (long)HEADS * VD * S_LEN)   // +4,194,304
#define SCRATCH_FLOATS (OFF_CTX + (long)S_LEN * HID)     // +4,194,304 = 39,976,960

__device__ __align__(256) float g_scratch[SCRATCH_FLOATS];

// ---------------------------------------------------------------------------
// Generic tiled SGEMM: C[M,N] = scale * (A[M,K] @ B[N,K]^T) + bias[n]
// BM=128, BN=64, BK=16, 256 threads, 8x4 micro-tile per thread.
// Batched via blockIdx.z with element strides sA/sB/sC.
// CAUSAL_SKIP: skip blocks fully above the diagonal (QK).
// CAUSAL_KLIM: clamp K loop to row0+BM (PV over causal-zeroed attn).
// Requires: M%128==0, N%64==0, K%16==0, all pointers 16B aligned, lds %4==0.
// ---------------------------------------------------------------------------
template<bool CAUSAL_SKIP, bool CAUSAL_KLIM>
__global__ __launch_bounds__(256)
void gemm_nt(const float* __restrict__ A, long sA,
             const float* __restrict__ B, long sB,
             float* __restrict__ C, long sC,
             int M, int N, int K,
             int lda, int ldb, int ldc,
             const float* __restrict__ bias, float scale)
{
    const int bz = blockIdx.z;
    A += (long)bz * sA;
    B += (long)bz * sB;
    C += (long)bz * sC;

    const int row0 = blockIdx.y * 128;
    const int col0 = blockIdx.x * 64;
    if (CAUSAL_SKIP && col0 >= row0 + 128) return;

    __shared__ float As[16][132];
    __shared__ float Bs[16][68];

    const int tid = threadIdx.x;
    const int ty = tid >> 4;       // 0..15 -> row group of 8
    const int tx = tid & 15;       // 0..15 -> col group of 4

    float acc[8][4];
#pragma unroll
    for (int i = 0; i < 8; i++)
#pragma unroll
        for (int j = 0; j < 4; j++) acc[i][j] = 0.f;

    int kEnd = K;
    if (CAUSAL_KLIM) kEnd = min(K, row0 + 128);

    for (int k0 = 0; k0 < kEnd; k0 += 16) {
        // A tile: 128 rows x 16 cols = 512 float4, 2 per thread
#pragma unroll
        for (int i = 0; i < 2; i++) {
            int f = tid * 2 + i;
            int r = f >> 2;
            int kg = (f & 3) * 4;
            float4 v = *reinterpret_cast<const float4*>(
                &A[(long)(row0 + r) * lda + k0 + kg]);
            As[kg + 0][r] = v.x; As[kg + 1][r] = v.y;
            As[kg + 2][r] = v.z; As[kg + 3][r] = v.w;
        }
        // B tile: 64 rows x 16 cols = 256 float4, 1 per thread
        {
            int r = tid >> 2;
            int kg = (tid & 3) * 4;
            float4 v = *reinterpret_cast<const float4*>(
                &B[(long)(col0 + r) * ldb + k0 + kg]);
            Bs[kg + 0][r] = v.x; Bs[kg + 1][r] = v.y;
            Bs[kg + 2][r] = v.z; Bs[kg + 3][r] = v.w;
        }
        __syncthreads();

#pragma unroll
        for (int k = 0; k < 16; k++) {
            float a[8], b[4];
#pragma unroll
            for (int i = 0; i < 8; i++) a[i] = As[k][ty * 8 + i];
#pragma unroll
            for (int j = 0; j < 4; j++) b[j] = Bs[k][tx * 4 + j];
#pragma unroll
            for (int i = 0; i < 8; i++)
#pragma unroll
                for (int j = 0; j < 4; j++)
                    acc[i][j] = fmaf(a[i], b[j], acc[i][j]);
        }
        __syncthreads();
    }

#pragma unroll
    for (int i = 0; i < 8; i++) {
        int r = row0 + ty * 8 + i;
#pragma unroll
        for (int j = 0; j < 4; j++) {
            int c = col0 + tx * 4 + j;
            float v = acc[i][j] * scale;
            if (bias) v += bias[c];
            C[(long)r * ldc + c] = v;
        }
    }
}

// ---------------------------------------------------------------------------
// Row-wise RMSNorm in place: x = g * x * rsqrt(mean(x^2) + eps) over n cols.
// One block (256 threads) per row; ld = row stride.
// ---------------------------------------------------------------------------
__global__ void rmsnorm_rows(float* __restrict__ X, const float* __restrict__ g,
                             int n, int ld)
{
    float* x = X + (long)blockIdx.x * ld;
    __shared__ float red[256];
    float s = 0.f;
    for (int i = threadIdx.x; i < n; i += 256) { float v = x[i]; s += v * v; }
    red[threadIdx.x] = s;
    __syncthreads();
    for (int o = 128; o > 0; o >>= 1) {
        if (threadIdx.x < o) red[threadIdx.x] += red[threadIdx.x + o];
        __syncthreads();
    }
    float r = rsqrtf(red[0] / (float)n + 1e-6f);
    for (int i = threadIdx.x; i < n; i += 256) x[i] = g[i] * x[i] * r;
}

// ---------------------------------------------------------------------------
// Assemble + RoPE. One block per position s (256 threads).
//  qall[h][s][0:128]=q_nope, [128:192]=roped q_rope
//  kall[h][s][0:128]=k_nope, [128:192]=roped shared k_rope
//  vt  [h][d][s] = v (transposed so PV uses the NT gemm)
// interleave_to_half + rotate_half collapse to:
//  out[k]    = x[2k]*cos_k   - x[2k+1]*sin_k      (k<32)
//  out[32+k] = x[2k+1]*cos_k + x[2k]*sin_k
// ---------------------------------------------------------------------------
__global__ void assemble_rope(const float* __restrict__ q,
                              const float* __restrict__ kvd,
                              const float* __restrict__ kv,
                              const int* __restrict__ pos_ids,
                              float* __restrict__ qall,
                              float* __restrict__ kall,
                              float* __restrict__ vt)
{
    const int s = blockIdx.x;
    const int t = threadIdx.x;
    __shared__ float cs[32], sn[32], kr[64];

    if (t < 32) {
        float pos = (float)pos_ids[s];
        double freq = exp(-log(10000.0) * (double)t / 32.0);
        float arg = pos * (float)freq;
        cs[t] = cosf(arg);
        sn[t] = sinf(arg);
    }
    __syncthreads();
    if (t < 32) {
        float x0 = kvd[(long)s * KVD_W + KVLR + 2 * t];
        float x1 = kvd[(long)s * KVD_W + KVLR + 2 * t + 1];
        kr[t]      = x0 * cs[t] - x1 * sn[t];
        kr[32 + t] = x1 * cs[t] + x0 * sn[t];
    }
    __syncthreads();

    for (int idx = t; idx < HEADS * QD; idx += 256) {
        int h = idx / QD, d = idx % QD;
        float qa, ka;
        if (d < NOPE) {
            qa = q[(long)s * QUP_N + h * QD + d];
            ka = kv[(long)s * KUP_N + h * (NOPE + VD) + d];
        } else {
            int k = d - NOPE;          // 0..63
            int kk = k & 31;
            float x0 = q[(long)s * QUP_N + h * QD + NOPE + 2 * kk];
            float x1 = q[(long)s * QUP_N + h * QD + NOPE + 2 * kk + 1];
            qa = (k < 32) ? (x0 * cs[kk] - x1 * sn[kk])
                          : (x1 * cs[kk] + x0 * sn[kk]);
            ka = kr[k];
        }
        qall[((long)h * S_LEN + s) * QD + d] = qa;
        kall[((long)h * S_LEN + s) * QD + d] = ka;
    }
    for (int idx = t; idx < HEADS * VD; idx += 256) {
        int h = idx / VD, d = idx % VD;
        vt[((long)h * VD + d) * S_LEN + s] =
            kv[(long)s * KUP_N + h * (NOPE + VD) + NOPE + d];
    }
}

// ---------------------------------------------------------------------------
// Causal softmax: one block per (head,row). Normalizes cols [0, i], zeros the
// rest (also covers blocks the QK gemm skipped entirely).
// ---------------------------------------------------------------------------
__global__ void softmax_causal(float* __restrict__ attn)
{
    const long row = blockIdx.x;          // 0 .. 16*2048-1
    const int i = (int)(row & (S_LEN - 1));
    float* p = attn + row * S_LEN;
    const int n = i + 1;
    __shared__ float red[256];

    float mx = -INFINITY;
    for (int j = threadIdx.x; j < n; j += 256) mx = fmaxf(mx, p[j]);
    red[threadIdx.x] = mx;
    __syncthreads();
    for (int o = 128; o > 0; o >>= 1) {
        if (threadIdx.x < o)
            red[threadIdx.x] = fmaxf(red[threadIdx.x], red[threadIdx.x + o]);
        __syncthreads();
    }
    mx = red[0];
    __syncthreads();

    float s = 0.f;
    for (int j = threadIdx.x; j < n; j += 256) {
        float e = expf(p[j] - mx);
        p[j] = e;
        s += e;
    }
    red[threadIdx.x] = s;
    __syncthreads();
    for (int o = 128; o > 0; o >>= 1) {
        if (threadIdx.x < o) red[threadIdx.x] += red[threadIdx.x + o];
        __syncthreads();
    }
    float inv = 1.f / red[0];
    for (int j = threadIdx.x; j < n; j += 256) p[j] *= inv;
    for (int j = n + threadIdx.x; j < S_LEN; j += 256) p[j] = 0.f;
}

// ---------------------------------------------------------------------------
extern "C" void kernel_launch(void* const* d_in, const int* in_sizes, int n_in,
                              void* d_out, int out_size)
{
    (void)in_sizes; (void)n_in; (void)out_size;
    const float* hid  = (const float*)d_in[0];
    const int*   pos  = (const int*)  d_in[1];
    // d_in[2] causal_mask: deterministic tril, enforced analytically
    const float* Wqd  = (const float*)d_in[3];
    const float* bqd  = (const float*)d_in[4];
    const float* gq   = (const float*)d_in[5];
    const float* Wqu  = (const float*)d_in[6];
    const float* Wkd  = (const float*)d_in[7];
    const float* bkd  = (const float*)d_in[8];
    const float* gkv  = (const float*)d_in[9];
    const float* Wku  = (const float*)d_in[10];
    const float* Wo   = (const float*)d_in[11];

    float* out  = (float*)d_out;
    float* attn = out + (long)S_LEN * HID;

    void* sp = nullptr;
    cudaGetSymbolAddress(&sp, g_scratch);
    float* scr  = (float*)sp;
    float* qraw = scr + OFF_QRAW;
    float* qbuf = scr + OFF_Q;
    float* kvd  = scr + OFF_KVD;
    float* kv   = scr + OFF_KV;
    float* qall = scr + OFF_QALL;
    float* kall = scr + OFF_KALL;
    float* vt   = scr + OFF_VT;
    float* ctx  = scr + OFF_CTX;

    const dim3 blk(256);
    const float qk_scale = 0.07216878364870323f;   // 1/sqrt(192)

    // 1. qraw = hid @ Wq_down^T + bq
    gemm_nt<false,false><<<dim3(QLR/64, S_LEN/128, 1), blk>>>(
        hid, 0, Wqd, 0, qraw, 0, S_LEN, QLR, HID, HID, HID, QLR, bqd, 1.f);
    // 2. rmsnorm in place
    rmsnorm_rows<<<S_LEN, blk>>>(qraw, gq, QLR, QLR);
    // 3. q = qraw @ Wq_up^T
    gemm_nt<false,false><<<dim3(QUP_N/64, S_LEN/128, 1), blk>>>(
        qraw, 0, Wqu, 0, qbuf, 0, S_LEN, QUP_N, QLR, QLR, QLR, QUP_N, nullptr, 1.f);
    // 4. kvd = hid @ Wkv_down^T + bkv
    gemm_nt<false,false><<<dim3(KVD_W/64, S_LEN/128, 1), blk>>>(
        hid, 0, Wkd, 0, kvd, 0, S_LEN, KVD_W, HID, HID, HID, KVD_W, bkd, 1.f);
    // 5. rmsnorm first 512 cols in place (rope tail untouched)
    rmsnorm_rows<<<S_LEN, blk>>>(kvd, gkv, KVLR, KVD_W);
    // 6. kv = kvd[:, :512] @ Wkv_up^T
    gemm_nt<false,false><<<dim3(KUP_N/64, S_LEN/128, 1), blk>>>(
        kvd, 0, Wku, 0, kv, 0, S_LEN, KUP_N, KVLR, KVD_W, KVLR, KUP_N, nullptr, 1.f);
    // 7. assemble + rope
    assemble_rope<<<S_LEN, blk>>>(qbuf, kvd, kv, pos, qall, kall, vt);
    // 8. scores -> attn region (batched over heads, causal block skip)
    gemm_nt<true,false><<<dim3(S_LEN/64, S_LEN/128, HEADS), blk>>>(
        qall, (long)S_LEN * QD, kall, (long)S_LEN * QD,
        attn, (long)S_LEN * S_LEN,
        S_LEN, S_LEN, QD, QD, QD, S_LEN, nullptr, qk_scale);
    // 9. causal softmax (writes zeros above diagonal)
    softmax_causal<<<HEADS * S_LEN, blk>>>(attn);
    // 10. ctx = attn @ v (K clamped at diagonal); ctx layout [s][h*128]
    gemm_nt<false,true><<<dim3(VD/64, S_LEN/128, HEADS), blk>>>(
        attn, (long)S_LEN * S_LEN, vt, (long)VD * S_LEN,
        ctx, (long)VD,
        S_LEN, VD, S_LEN, S_LEN, S_LEN, HID, nullptr, 1.f);
    // 11. out = ctx @ Wo^T
    gemm_nt<false,false><<<dim3(HID/64, S_LEN/128, 1), blk>>>(
        ctx, 0, Wo, 0, out, 0, S_LEN, HID, HID, HID, HID, HID, nullptr, 1.f);
}

// round 2
// speedup vs baseline: 1.9551x; 1.9551x over previous
#include <cuda_runtime.h>
#include <cuda_bf16.h>
#include <math.h>
#include <stdint.h>

// ---------------------------------------------------------------------------
// DeepseekV2 MLA forward, B=1 S=2048 HID=2048 H=16 NOPE=128 ROPE=64 VD=128
// QD=192 QLR=1536 KVLR=512. Outputs: out [1,2048,2048] fp32 then
// attn [1,16,2048,2048] fp32, concatenated in d_out.
//
// Round 2: all GEMMs moved to tensor cores. mma.sync.m16n8k16 bf16 with
// 2-term bf16 split (hi+lo) and 3 mma accumulation passes per k-chunk:
//   D += Ahi*Bhi + Ahi*Blo + Alo*Bhi   (fp32 accumulators)
// giving ~2^-16 relative error per product — well inside 1e-3 budget.
// ---------------------------------------------------------------------------

#define S_LEN 2048
#define HID   2048
#define HEADS 16
#define NOPE  128
#define ROPE  64
#define VD    128
#define QD    192
#define QLR   1536
#define KVLR  512
#define KVD_W (KVLR + ROPE)   // 576
#define QUP_N (HEADS * QD)    // 3072
#define KUP_N (HEADS * (NOPE + VD)) // 4096

// scratch layout (floats)
#define OFF_QRAW 0L
#define OFF_Q    (OFF_QRAW + (long)S_LEN * QLR)
#define OFF_KVD  (OFF_Q    + (long)S_LEN * QUP_N)
#define OFF_KV   (OFF_KVD  + (long)S_LEN * KVD_W)
#define OFF_QALL (OFF_KV   + (long)S_LEN * KUP_N)
#define OFF_KALL (OFF_QALL + (long)HEADS * S_LEN * QD)
#define OFF_VT   (OFF_KALL + (long)HEADS * S_LEN * QD)
#define OFF_CTX  (OFF_VT   + (long)HEADS * VD * S_LEN)
#define SCRATCH_FLOATS (OFF_CTX + (long)S_LEN * HID)

__device__ __align__(256) float g_scratch[SCRATCH_FLOATS];

// ---------------------------------------------------------------------------
// helpers
// ---------------------------------------------------------------------------
__device__ __forceinline__ unsigned smem_u32(const void* p) {
    return (unsigned)__cvta_generic_to_shared(p);
}

__device__ __forceinline__ void ldm_x4(uint32_t r[4], unsigned addr) {
    asm volatile("ldmatrix.sync.aligned.m8n8.x4.shared.b16 {%0,%1,%2,%3}, [%4];"
                 : "=r"(r[0]), "=r"(r[1]), "=r"(r[2]), "=r"(r[3]) : "r"(addr));
}

__device__ __forceinline__ void mma16816(float d[4], const uint32_t a[4],
                                         const uint32_t b[2]) {
    asm volatile(
        "mma.sync.aligned.m16n8k16.row.col.f32.bf16.bf16.f32 "
        "{%0,%1,%2,%3}, {%4,%5,%6,%7}, {%8,%9}, {%0,%1,%2,%3};"
        : "+f"(d[0]), "+f"(d[1]), "+f"(d[2]), "+f"(d[3])
        : "r"(a[0]), "r"(a[1]), "r"(a[2]), "r"(a[3]), "r"(b[0]), "r"(b[1]));
}

// split a float4 into bf16 hi/lo and store 4+4 bf16 (8B each) to smem
__device__ __forceinline__ void cvt_store(__nv_bfloat16* dh, __nv_bfloat16* dl,
                                          float4 v) {
    __nv_bfloat162 h01 = __floats2bfloat162_rn(v.x, v.y);
    __nv_bfloat162 h23 = __floats2bfloat162_rn(v.z, v.w);
    float lx = v.x - __low2float(h01);
    float ly = v.y - __high2float(h01);
    float lz = v.z - __low2float(h23);
    float lw = v.w - __high2float(h23);
    __nv_bfloat162 l01 = __floats2bfloat162_rn(lx, ly);
    __nv_bfloat162 l23 = __floats2bfloat162_rn(lz, lw);
    uint2 uh, ul;
    uh.x = *(uint32_t*)&h01; uh.y = *(uint32_t*)&h23;
    ul.x = *(uint32_t*)&l01; ul.y = *(uint32_t*)&l23;
    *(uint2*)dh = uh;
    *(uint2*)dl = ul;
}

// ---------------------------------------------------------------------------
// Tensor-core GEMM: C[M,N] = scale * (A[M,K] @ B[N,K]^T) + bias[n]
// BM=128, BN=64, BK=16, 256 threads (8 warps, 4x2, each warp 32x32).
// bf16 hi/lo split, 3 mma passes, fp32 accum. Double-buffered smem.
// Row stride 24 bf16 (48B) for conflict-free ldmatrix.
// Requires: M%128==0, N%64==0, K%16==0.
// ---------------------------------------------------------------------------
#define ASTR 24
template<bool CSKIP, bool CKLIM>
__global__ __launch_bounds__(256)
void gemm_tc(const float* __restrict__ A, long sA,
             const float* __restrict__ B, long sB,
             float* __restrict__ C, long sC,
             int M, int N, int K,
             int lda, int ldb, int ldc,
             const float* __restrict__ bias, float scale)
{
    const int bz = blockIdx.z;
    A += (long)bz * sA;
    B += (long)bz * sB;
    C += (long)bz * sC;

    const int row0 = blockIdx.y * 128;
    const int col0 = blockIdx.x * 64;
    if (CSKIP && col0 >= row0 + 128) return;

    __shared__ __nv_bfloat16 Ah[2][128 * ASTR];
    __shared__ __nv_bfloat16 Al[2][128 * ASTR];
    __shared__ __nv_bfloat16 Bh[2][64 * ASTR];
    __shared__ __nv_bfloat16 Bl[2][64 * ASTR];

    const int tid  = threadIdx.x;
    const int wid  = tid >> 5;
    const int lane = tid & 31;
    const int wm   = wid >> 1;     // 0..3 : rows wm*32
    const int wn   = wid & 1;      // 0..1 : cols wn*32

    float acc[2][4][4];
#pragma unroll
    for (int i = 0; i < 2; i++)
#pragma unroll
        for (int j = 0; j < 4; j++)
#pragma unroll
            for (int k = 0; k < 4; k++) acc[i][j][k] = 0.f;

    int kEnd = K;
    if (CKLIM) kEnd = min(K, row0 + 128);
    const int nc = kEnd >> 4;

    // global load indices: A row tid/2, k-base (tid&1)*8 (two float4)
    //                      B row tid/4, k-base (tid&3)*4 (one float4)
    const int a_r  = tid >> 1;
    const int a_kb = (tid & 1) << 3;
    const int b_r  = tid >> 2;
    const int b_kb = (tid & 3) << 2;
    const float* Abase = A + (long)(row0 + a_r) * lda + a_kb;
    const float* Bbase = B + (long)(col0 + b_r) * ldb + b_kb;
    const int a_so = a_r * ASTR + a_kb;
    const int b_so = b_r * ASTR + b_kb;

    float4 ra0, ra1, rb0;
    {
        ra0 = *(const float4*)(Abase);
        ra1 = *(const float4*)(Abase + 4);
        rb0 = *(const float4*)(Bbase);
        cvt_store(&Ah[0][a_so],     &Al[0][a_so],     ra0);
        cvt_store(&Ah[0][a_so + 4], &Al[0][a_so + 4], ra1);
        cvt_store(&Bh[0][b_so],     &Bl[0][b_so],     rb0);
    }
    __syncthreads();

    // ldmatrix shared addresses (per warp, fixed offsets within a buffer)
    const int a_row_in = (lane & 15);
    const int a_k8     = (lane >> 4) << 3;
    const int b_row_in = (lane & 7) + ((lane >> 4) << 3);
    const int b_k8     = ((lane >> 3) & 1) << 3;

    int buf = 0;
    for (int c = 0; c < nc; ++c) {
        if (c + 1 < nc) {
            const float* Ap = Abase + ((c + 1) << 4);
            const float* Bp = Bbase + ((c + 1) << 4);
            ra0 = *(const float4*)(Ap);
            ra1 = *(const float4*)(Ap + 4);
            rb0 = *(const float4*)(Bp);
        }

        // ---- compute on buf ----
        uint32_t afh[2][4], afl[2][4];
#pragma unroll
        for (int mi = 0; mi < 2; mi++) {
            int r = (wm * 32 + mi * 16 + a_row_in) * ASTR + a_k8;
            ldm_x4(afh[mi], smem_u32(&Ah[buf][r]));
            ldm_x4(afl[mi], smem_u32(&Al[buf][r]));
        }
        uint32_t bfh[4][2], bfl[4][2];
#pragma unroll
        for (int g = 0; g < 2; g++) {
            int r = (wn * 32 + g * 16 + b_row_in) * ASTR + b_k8;
            uint32_t t[4];
            ldm_x4(t, smem_u32(&Bh[buf][r]));
            bfh[2 * g][0] = t[0]; bfh[2 * g][1] = t[1];
            bfh[2 * g + 1][0] = t[2]; bfh[2 * g + 1][1] = t[3];
            ldm_x4(t, smem_u32(&Bl[buf][r]));
            bfl[2 * g][0] = t[0]; bfl[2 * g][1] = t[1];
            bfl[2 * g + 1][0] = t[2]; bfl[2 * g + 1][1] = t[3];
        }
#pragma unroll
        for (int mi = 0; mi < 2; mi++)
#pragma unroll
            for (int ni = 0; ni < 4; ni++) {
                mma16816(acc[mi][ni], afh[mi], bfh[ni]);
                mma16816(acc[mi][ni], afh[mi], bfl[ni]);
                mma16816(acc[mi][ni], afl[mi], bfh[ni]);
            }

        if (c + 1 < nc) {
            int nb = buf ^ 1;
            cvt_store(&Ah[nb][a_so],     &Al[nb][a_so],     ra0);
            cvt_store(&Ah[nb][a_so + 4], &Al[nb][a_so + 4], ra1);
            cvt_store(&Bh[nb][b_so],     &Bl[nb][b_so],     rb0);
            __syncthreads();
        }
        buf ^= 1;
    }

    // ---- epilogue ----
#pragma unroll
    for (int mi = 0; mi < 2; mi++) {
        int rbase = row0 + wm * 32 + mi * 16 + (lane >> 2);
#pragma unroll
        for (int ni = 0; ni < 4; ni++) {
            int cc = col0 + wn * 32 + ni * 8 + ((lane & 3) << 1);
            float b0 = 0.f, b1 = 0.f;
            if (bias) { b0 = bias[cc]; b1 = bias[cc + 1]; }
            float2 v0, v1;
            v0.x = acc[mi][ni][0] * scale + b0;
            v0.y = acc[mi][ni][1] * scale + b1;
            v1.x = acc[mi][ni][2] * scale + b0;
            v1.y = acc[mi][ni][3] * scale + b1;
            *(float2*)&C[(long)rbase * ldc + cc]       = v0;
            *(float2*)&C[(long)(rbase + 8) * ldc + cc] = v1;
        }
    }
}

// ---------------------------------------------------------------------------
// Row-wise RMSNorm in place
// ---------------------------------------------------------------------------
__global__ void rmsnorm_rows(float* __restrict__ X, const float* __restrict__ g,
                             int n, int ld)
{
    float* x = X + (long)blockIdx.x * ld;
    __shared__ float red[256];
    float s = 0.f;
    for (int i = threadIdx.x; i < n; i += 256) { float v = x[i]; s += v * v; }
    red[threadIdx.x] = s;
    __syncthreads();
    for (int o = 128; o > 0; o >>= 1) {
        if (threadIdx.x < o) red[threadIdx.x] += red[threadIdx.x + o];
        __syncthreads();
    }
    float r = rsqrtf(red[0] / (float)n + 1e-6f);
    for (int i = threadIdx.x; i < n; i += 256) x[i] = g[i] * x[i] * r;
}

// ---------------------------------------------------------------------------
// Assemble + RoPE (see R1 comments)
// ---------------------------------------------------------------------------
__global__ void assemble_rope(const float* __restrict__ q,
                              const float* __restrict__ kvd,
                              const float* __restrict__ kv,
                              const int* __restrict__ pos_ids,
                              float* __restrict__ qall,
                              float* __restrict__ kall,
                              float* __restrict__ vt)
{
    const int s = blockIdx.x;
    const int t = threadIdx.x;
    __shared__ float cs[32], sn[32], kr[64];

    if (t < 32) {
        float pos = (float)pos_ids[s];
        double freq = exp(-log(10000.0) * (double)t / 32.0);
        float arg = pos * (float)freq;
        cs[t] = cosf(arg);
        sn[t] = sinf(arg);
    }
    __syncthreads();
    if (t < 32) {
        float x0 = kvd[(long)s * KVD_W + KVLR + 2 * t];
        float x1 = kvd[(long)s * KVD_W + KVLR + 2 * t + 1];
        kr[t]      = x0 * cs[t] - x1 * sn[t];
        kr[32 + t] = x1 * cs[t] + x0 * sn[t];
    }
    __syncthreads();

    for (int idx = t; idx < HEADS * QD; idx += 256) {
        int h = idx / QD, d = idx % QD;
        float qa, ka;
        if (d < NOPE) {
            qa = q[(long)s * QUP_N + h * QD + d];
            ka = kv[(long)s * KUP_N + h * (NOPE + VD) + d];
        } else {
            int k = d - NOPE;
            int kk = k & 31;
            float x0 = q[(long)s * QUP_N + h * QD + NOPE + 2 * kk];
            float x1 = q[(long)s * QUP_N + h * QD + NOPE + 2 * kk + 1];
            qa = (k < 32) ? (x0 * cs[kk] - x1 * sn[kk])
                          : (x1 * cs[kk] + x0 * sn[kk]);
            ka = kr[k];
        }
        qall[((long)h * S_LEN + s) * QD + d] = qa;
        kall[((long)h * S_LEN + s) * QD + d] = ka;
    }
    for (int idx = t; idx < HEADS * VD; idx += 256) {
        int h = idx / VD, d = idx % VD;
        vt[((long)h * VD + d) * S_LEN + s] =
            kv[(long)s * KUP_N + h * (NOPE + VD) + NOPE + d];
    }
}

// ---------------------------------------------------------------------------
// Causal softmax: one block per (head,row)
// ---------------------------------------------------------------------------
__global__ void softmax_causal(float* __restrict__ attn)
{
    const long row = blockIdx.x;
    const int i = (int)(row & (S_LEN - 1));
    float* p = attn + row * S_LEN;
    const int n = i + 1;
    __shared__ float red[256];

    float mx = -INFINITY;
    for (int j = threadIdx.x; j < n; j += 256) mx = fmaxf(mx, p[j]);
    red[threadIdx.x] = mx;
    __syncthreads();
    for (int o = 128; o > 0; o >>= 1) {
        if (threadIdx.x < o)
            red[threadIdx.x] = fmaxf(red[threadIdx.x], red[threadIdx.x + o]);
        __syncthreads();
    }
    mx = red[0];
    __syncthreads();

    float s = 0.f;
    for (int j = threadIdx.x; j < n; j += 256) {
        float e = expf(p[j] - mx);
        p[j] = e;
        s += e;
    }
    red[threadIdx.x] = s;
    __syncthreads();
    for (int o = 128; o > 0; o >>= 1) {
        if (threadIdx.x < o) red[threadIdx.x] += red[threadIdx.x + o];
        __syncthreads();
    }
    float inv = 1.f / red[0];
    for (int j = threadIdx.x; j < n; j += 256) p[j] *= inv;
    for (int j = n + threadIdx.x; j < S_LEN; j += 256) p[j] = 0.f;
}

// ---------------------------------------------------------------------------
extern "C" void kernel_launch(void* const* d_in, const int* in_sizes, int n_in,
                              void* d_out, int out_size)
{
    (void)in_sizes; (void)n_in; (void)out_size;
    const float* hid  = (const float*)d_in[0];
    const int*   pos  = (const int*)  d_in[1];
    const float* Wqd  = (const float*)d_in[3];
    const float* bqd  = (const float*)d_in[4];
    const float* gq   = (const float*)d_in[5];
    const float* Wqu  = (const float*)d_in[6];
    const float* Wkd  = (const float*)d_in[7];
    const float* bkd  = (const float*)d_in[8];
    const float* gkv  = (const float*)d_in[9];
    const float* Wku  = (const float*)d_in[10];
    const float* Wo   = (const float*)d_in[11];

    float* out  = (float*)d_out;
    float* attn = out + (long)S_LEN * HID;

    void* sp = nullptr;
    cudaGetSymbolAddress(&sp, g_scratch);
    float* scr  = (float*)sp;
    float* qraw = scr + OFF_QRAW;
    float* qbuf = scr + OFF_Q;
    float* kvd  = scr + OFF_KVD;
    float* kv   = scr + OFF_KV;
    float* qall = scr + OFF_QALL;
    float* kall = scr + OFF_KALL;
    float* vt   = scr + OFF_VT;
    float* ctx  = scr + OFF_CTX;

    const dim3 blk(256);
    const float qk_scale = 0.07216878364870323f;   // 1/sqrt(192)

    // 1. qraw = hid @ Wq_down^T + bq
    gemm_tc<false,false><<<dim3(QLR/64, S_LEN/128, 1), blk>>>(
        hid, 0, Wqd, 0, qraw, 0, S_LEN, QLR, HID, HID, HID, QLR, bqd, 1.f);
    // 2. rmsnorm in place
    rmsnorm_rows<<<S_LEN, blk>>>(qraw, gq, QLR, QLR);
    // 3. q = qraw @ Wq_up^T
    gemm_tc<false,false><<<dim3(QUP_N/64, S_LEN/128, 1), blk>>>(
        qraw, 0, Wqu, 0, qbuf, 0, S_LEN, QUP_N, QLR, QLR, QLR, QUP_N, nullptr, 1.f);
    // 4. kvd = hid @ Wkv_down^T + bkv
    gemm_tc<false,false><<<dim3(KVD_W/64, S_LEN/128, 1), blk>>>(
        hid, 0, Wkd, 0, kvd, 0, S_LEN, KVD_W, HID, HID, HID, KVD_W, bkd, 1.f);
    // 5. rmsnorm first 512 cols in place
    rmsnorm_rows<<<S_LEN, blk>>>(kvd, gkv, KVLR, KVD_W);
    // 6. kv = kvd[:, :512] @ Wkv_up^T
    gemm_tc<false,false><<<dim3(KUP_N/64, S_LEN/128, 1), blk>>>(
        kvd, 0, Wku, 0, kv, 0, S_LEN, KUP_N, KVLR, KVD_W, KVLR, KUP_N, nullptr, 1.f);
    // 7. assemble + rope
    assemble_rope<<<S_LEN, blk>>>(qbuf, kvd, kv, pos, qall, kall, vt);
    // 8. scores -> attn region (batched over heads, causal block skip)
    gemm_tc<true,false><<<dim3(S_LEN/64, S_LEN/128, HEADS), blk>>>(
        qall, (long)S_LEN * QD, kall, (long)S_LEN * QD,
        attn, (long)S_LEN * S_LEN,
        S_LEN, S_LEN, QD, QD, QD, S_LEN, nullptr, qk_scale);
    // 9. causal softmax
    softmax_causal<<<HEADS * S_LEN, blk>>>(attn);
    // 10. ctx = attn @ v (K clamped at diagonal)
    gemm_tc<false,true><<<dim3(VD/64, S_LEN/128, HEADS), blk>>>(
        attn, (long)S_LEN * S_LEN, vt, (long)VD * S_LEN,
        ctx, (long)VD,
        S_LEN, VD, S_LEN, S_LEN, S_LEN, HID, nullptr, 1.f);
    // 11. out = ctx @ Wo^T
    gemm_tc<false,false><<<dim3(HID/64, S_LEN/128, 1), blk>>>(
        ctx, 0, Wo, 0, out, 0, S_LEN, HID, HID, HID, HID, HID, nullptr, 1.f);
}

// round 4
// speedup vs baseline: 2.0440x; 1.0455x over previous
#include <cuda_runtime.h>
#include <cuda_bf16.h>
#include <math.h>
#include <stdint.h>

// ---------------------------------------------------------------------------
// DeepseekV2 MLA forward, B=1 S=2048 HID=2048 H=16 NOPE=128 ROPE=64 VD=128.
// Round 4: Round-3 design with the pipeline slot bug fixed (stage s must land
// in smem slot s % STAGES; R3 wrote prefetches into the just-consumed slot,
// leaving slot 2 uninitialized -> NaN).
// Operands pre-split to bf16 hi/lo in GMEM (once); tensor-core GEMM with
// BM=128 BN={64,128} BK=32, 3-stage cp.async pipeline, 3-pass compensated
// bf16 mma (Ahi*Bhi + Ahi*Blo + Alo*Bhi, fp32 accum).
// ---------------------------------------------------------------------------

#define S_LEN 2048
#define HID   2048
#define HEADS 16
#define NOPE  128
#define ROPE  64
#define VD    128
#define QD    192
#define QLR   1536
#define KVLR  512
#define KVD_W (KVLR + ROPE)          // 576
#define QUP_N (HEADS * QD)           // 3072
#define KUP_N (HEADS * (NOPE + VD))  // 4096

// ---------------- fp32 scratch ----------------
#define F_QRAW 0L
#define F_QBUF (F_QRAW + (long)S_LEN * QLR)
#define F_KVD  (F_QBUF + (long)S_LEN * QUP_N)
#define F_KV   (F_KVD  + (long)S_LEN * KVD_W)
#define F_CTX  (F_KV   + (long)S_LEN * KUP_N)
#define F_TOT  (F_CTX  + (long)S_LEN * HID)

// ---------------- bf16 hi/lo scratch (same offsets in H and L arrays) ------
#define O_HID  0L
#define O_WQD  (O_HID  + (long)S_LEN * HID)
#define O_WQU  (O_WQD  + (long)QLR * HID)
#define O_WKD  (O_WQU  + (long)QUP_N * QLR)
#define O_WKU  (O_WKD  + (long)KVD_W * HID)
#define O_WO   (O_WKU  + (long)KUP_N * KVLR)
#define O_QRN  (O_WO   + (long)HID * (HEADS * VD))
#define O_KVN  (O_QRN  + (long)S_LEN * QLR)
#define O_QALL (O_KVN  + (long)S_LEN * KVLR)
#define O_KALL (O_QALL + (long)HEADS * S_LEN * QD)
#define O_VT   (O_KALL + (long)HEADS * S_LEN * QD)
#define O_ATTN (O_VT   + (long)HEADS * VD * S_LEN)
#define O_CTX  (O_ATTN + (long)HEADS * S_LEN * S_LEN)
#define O_TOT  (O_CTX  + (long)S_LEN * HID)

__device__ __align__(256) float         g_f32[F_TOT];
__device__ __align__(256) __nv_bfloat16 g_hi[O_TOT];
__device__ __align__(256) __nv_bfloat16 g_lo[O_TOT];

// ---------------------------------------------------------------------------
__device__ __forceinline__ unsigned smem_u32(const void* p) {
    return (unsigned)__cvta_generic_to_shared(p);
}
__device__ __forceinline__ void ldm_x4(uint32_t r[4], unsigned addr) {
    asm volatile("ldmatrix.sync.aligned.m8n8.x4.shared.b16 {%0,%1,%2,%3}, [%4];"
                 : "=r"(r[0]), "=r"(r[1]), "=r"(r[2]), "=r"(r[3]) : "r"(addr));
}
__device__ __forceinline__ void mma16816(float d[4], const uint32_t a[4],
                                         const uint32_t b[2]) {
    asm volatile(
        "mma.sync.aligned.m16n8k16.row.col.f32.bf16.bf16.f32 "
        "{%0,%1,%2,%3}, {%4,%5,%6,%7}, {%8,%9}, {%0,%1,%2,%3};"
        : "+f"(d[0]), "+f"(d[1]), "+f"(d[2]), "+f"(d[3])
        : "r"(a[0]), "r"(a[1]), "r"(a[2]), "r"(a[3]), "r"(b[0]), "r"(b[1]));
}
__device__ __forceinline__ void cp16(unsigned dst, const void* src) {
    asm volatile("cp.async.cg.shared.global [%0], [%1], 16;"
                 :: "r"(dst), "l"(src));
}
#define CP_COMMIT() asm volatile("cp.async.commit_group;" ::: "memory")
#define CP_WAIT1()  asm volatile("cp.async.wait_group 1;" ::: "memory")

__device__ __forceinline__ void split1(float v, __nv_bfloat16* h,
                                       __nv_bfloat16* l) {
    __nv_bfloat16 a = __float2bfloat16(v);
    *h = a;
    *l = __float2bfloat16(v - __bfloat162float(a));
}

// ---------------------------------------------------------------------------
// elementwise fp32 -> bf16 hi/lo split (n % 1024 == 0)
// ---------------------------------------------------------------------------
__global__ void split_hl(const float* __restrict__ x,
                         __nv_bfloat16* __restrict__ h,
                         __nv_bfloat16* __restrict__ l, long n)
{
    long i = ((long)blockIdx.x * 256 + threadIdx.x) * 4;
    if (i >= n) return;
    float4 v = *(const float4*)(x + i);
    __nv_bfloat162 h01 = __floats2bfloat162_rn(v.x, v.y);
    __nv_bfloat162 h23 = __floats2bfloat162_rn(v.z, v.w);
    __nv_bfloat162 l01 = __floats2bfloat162_rn(v.x - __low2float(h01),
                                               v.y - __high2float(h01));
    __nv_bfloat162 l23 = __floats2bfloat162_rn(v.z - __low2float(h23),
                                               v.w - __high2float(h23));
    uint2 uh, ul;
    uh.x = *(uint32_t*)&h01; uh.y = *(uint32_t*)&h23;
    ul.x = *(uint32_t*)&l01; ul.y = *(uint32_t*)&l23;
    *(uint2*)(h + i) = uh;
    *(uint2*)(l + i) = ul;
}

// ---------------------------------------------------------------------------
// Tensor-core GEMM: C[M,N] = scale*(A[M,K] @ B[N,K]^T) + bias,
// operands pre-split bf16 hi/lo. BM=128, BN in {64,128}, BK=32, 256 threads,
// 8 warps (4m x 2n), 3-stage cp.async pipeline. Optional hi/lo C output.
// ---------------------------------------------------------------------------
#define SST 40          // smem row stride in bf16 elements (80 B)
#define STAGES 3

template<int BN, bool CSKIP, bool CKLIM>
__global__ __launch_bounds__(256)
void gemm_hl(const __nv_bfloat16* __restrict__ Agh,
             const __nv_bfloat16* __restrict__ Agl, long sA,
             const __nv_bfloat16* __restrict__ Bgh,
             const __nv_bfloat16* __restrict__ Bgl, long sB,
             float* __restrict__ C, long sC,
             __nv_bfloat16* __restrict__ Ch, __nv_bfloat16* __restrict__ Cl,
             int K, int lda, int ldb, int ldc,
             const float* __restrict__ bias, float scale)
{
    extern __shared__ __nv_bfloat16 sm[];
    constexpr int WN = BN / 2;
    constexpr int NF = WN / 8;
    constexpr unsigned SSB = (unsigned)(256 + 2 * BN) * SST * 2; // stage bytes

    const int bz = blockIdx.z;
    Agh += (long)bz * sA;  Agl += (long)bz * sA;
    Bgh += (long)bz * sB;  Bgl += (long)bz * sB;
    C   += (long)bz * sC;
    if (Ch) { Ch += (long)bz * sC; Cl += (long)bz * sC; }

    const int row0 = blockIdx.y * 128;
    const int col0 = blockIdx.x * BN;
    if (CSKIP && col0 >= row0 + 128) return;

    int kEnd = CKLIM ? min(K, row0 + 128) : K;
    const int nc = kEnd >> 5;

    const int tid = threadIdx.x;
    const int wid = tid >> 5, lane = tid & 31;
    const int wm = wid & 3, wn = wid >> 2;

    // global load mapping: thread -> (row tid/4, 16B chunk tid%4)
    const int ar  = tid >> 2;
    const int acb = (tid & 3) * 8;
    const __nv_bfloat16* gAh = Agh + (long)(row0 + ar) * lda + acb;
    const __nv_bfloat16* gAl = Agl + (long)(row0 + ar) * lda + acb;
    const __nv_bfloat16* gBh = Bgh + (long)(col0 + ar) * ldb + acb;
    const __nv_bfloat16* gBl = Bgl + (long)(col0 + ar) * ldb + acb;

    const unsigned smb  = smem_u32(sm);
    const unsigned sAh0 = smb + (unsigned)(ar * SST + acb) * 2;
    const unsigned sAl0 = sAh0 + 128u * SST * 2;
    const unsigned sBh0 = smb + (unsigned)(256 * SST + ar * SST + acb) * 2;
    const unsigned sBl0 = sBh0 + (unsigned)BN * SST * 2;

    float acc[2][NF][4];
#pragma unroll
    for (int i = 0; i < 2; i++)
#pragma unroll
        for (int j = 0; j < NF; j++)
#pragma unroll
            for (int k = 0; k < 4; k++) acc[i][j][k] = 0.f;

    auto load_stage = [&](int kc, int s) {
        const int k0 = kc << 5;
        const unsigned so = (unsigned)s * SSB;
        cp16(sAh0 + so,                 gAh + k0);
        cp16(sAh0 + so + 64u*SST*2,     gAh + 64 * lda + k0);
        cp16(sAl0 + so,                 gAl + k0);
        cp16(sAl0 + so + 64u*SST*2,     gAl + 64 * lda + k0);
        cp16(sBh0 + so,                 gBh + k0);
        cp16(sBl0 + so,                 gBl + k0);
        if (BN == 128) {
            cp16(sBh0 + so + 64u*SST*2, gBh + 64 * ldb + k0);
            cp16(sBl0 + so + 64u*SST*2, gBl + 64 * ldb + k0);
        }
    };

#pragma unroll
    for (int s = 0; s < STAGES - 1; ++s) {
        if (s < nc) load_stage(s, s);
        CP_COMMIT();
    }

    // ldmatrix per-thread offsets
    const int a_ri = lane & 15;
    const int a_k8 = (lane >> 4) << 3;
    const int b_ri = (lane & 7) + ((lane >> 4) << 3);
    const int b_k8 = ((lane >> 3) & 1) << 3;

    int buf = 0;                 // compute slot: stage c lives in slot c%STAGES
    int ldslot = STAGES - 1;     // next prefetch slot: stage c+STAGES-1
    for (int c = 0; c < nc; ++c) {
        CP_WAIT1();
        __syncthreads();

        const unsigned so = (unsigned)buf * SSB;
#pragma unroll
        for (int kk = 0; kk < 2; kk++) {
            uint32_t ah[2][4], al[2][4];
#pragma unroll
            for (int mi = 0; mi < 2; mi++) {
                unsigned ad = smb + so +
                    (unsigned)((wm * 32 + mi * 16 + a_ri) * SST + kk * 16 + a_k8) * 2;
                ldm_x4(ah[mi], ad);
                ldm_x4(al[mi], ad + 128u * SST * 2);
            }
            uint32_t bh[NF][2], bl[NF][2];
#pragma unroll
            for (int g = 0; g < NF / 2; g++) {
                unsigned bd = smb + so + (unsigned)(256 * SST +
                    (wn * WN + g * 16 + b_ri) * SST + kk * 16 + b_k8) * 2;
                uint32_t t4[4];
                ldm_x4(t4, bd);
                bh[2*g][0] = t4[0]; bh[2*g][1] = t4[1];
                bh[2*g+1][0] = t4[2]; bh[2*g+1][1] = t4[3];
                ldm_x4(t4, bd + (unsigned)BN * SST * 2);
                bl[2*g][0] = t4[0]; bl[2*g][1] = t4[1];
                bl[2*g+1][0] = t4[2]; bl[2*g+1][1] = t4[3];
            }
#pragma unroll
            for (int mi = 0; mi < 2; mi++)
#pragma unroll
                for (int f = 0; f < NF; f++) {
                    mma16816(acc[mi][f], ah[mi], bh[f]);
                    mma16816(acc[mi][f], ah[mi], bl[f]);
                    mma16816(acc[mi][f], al[mi], bh[f]);
                }
        }
        __syncthreads();
        int nx = c + STAGES - 1;
        if (nx < nc) load_stage(nx, ldslot);
        CP_COMMIT();
        buf    = (buf    + 1 == STAGES) ? 0 : buf    + 1;
        ldslot = (ldslot + 1 == STAGES) ? 0 : ldslot + 1;
    }

    // epilogue
#pragma unroll
    for (int mi = 0; mi < 2; mi++) {
        const int rb = row0 + wm * 32 + mi * 16 + (lane >> 2);
#pragma unroll
        for (int f = 0; f < NF; f++) {
            const int cc = col0 + wn * WN + f * 8 + ((lane & 3) << 1);
            float b0 = 0.f, b1 = 0.f;
            if (bias) { b0 = bias[cc]; b1 = bias[cc + 1]; }
            float2 v0, v1;
            v0.x = acc[mi][f][0] * scale + b0;
            v0.y = acc[mi][f][1] * scale + b1;
            v1.x = acc[mi][f][2] * scale + b0;
            v1.y = acc[mi][f][3] * scale + b1;
            *(float2*)&C[(long)rb * ldc + cc]       = v0;
            *(float2*)&C[(long)(rb + 8) * ldc + cc] = v1;
            if (Ch) {
                __nv_bfloat16 h2[2], l2[2];
                split1(v0.x, &h2[0], &l2[0]); split1(v0.y, &h2[1], &l2[1]);
                *(uint32_t*)&Ch[(long)rb * ldc + cc] = *(uint32_t*)h2;
                *(uint32_t*)&Cl[(long)rb * ldc + cc] = *(uint32_t*)l2;
                split1(v1.x, &h2[0], &l2[0]); split1(v1.y, &h2[1], &l2[1]);
                *(uint32_t*)&Ch[(long)(rb + 8) * ldc + cc] = *(uint32_t*)h2;
                *(uint32_t*)&Cl[(long)(rb + 8) * ldc + cc] = *(uint32_t*)l2;
            }
        }
    }
}

// ---------------------------------------------------------------------------
// RMSNorm rows: read fp32 X (stride ldin, n cols), write bf16 hi/lo (stride n)
// ---------------------------------------------------------------------------
__global__ void rmsnorm_split(const float* __restrict__ X,
                              const float* __restrict__ g,
                              __nv_bfloat16* __restrict__ H,
                              __nv_bfloat16* __restrict__ L,
                              int n, int ldin)
{
    const float* x = X + (long)blockIdx.x * ldin;
    __nv_bfloat16* h = H + (long)blockIdx.x * n;
    __nv_bfloat16* l = L + (long)blockIdx.x * n;
    __shared__ float red[256];
    float s = 0.f;
    for (int i = threadIdx.x; i < n; i += 256) { float v = x[i]; s += v * v; }
    red[threadIdx.x] = s;
    __syncthreads();
    for (int o = 128; o > 0; o >>= 1) {
        if (threadIdx.x < o) red[threadIdx.x] += red[threadIdx.x + o];
        __syncthreads();
    }
    float r = rsqrtf(red[0] / (float)n + 1e-6f);
    for (int i = threadIdx.x; i < n; i += 256)
        split1(g[i] * x[i] * r, &h[i], &l[i]);
}

// ---------------------------------------------------------------------------
// Assemble + RoPE -> bf16 hi/lo qall/kall/vt
// ---------------------------------------------------------------------------
__global__ void assemble_rope(const float* __restrict__ q,
                              const float* __restrict__ kvd,
                              const float* __restrict__ kv,
                              const int* __restrict__ pos_ids,
                              __nv_bfloat16* __restrict__ qh, __nv_bfloat16* __restrict__ ql,
                              __nv_bfloat16* __restrict__ kh, __nv_bfloat16* __restrict__ kl,
                              __nv_bfloat16* __restrict__ vh, __nv_bfloat16* __restrict__ vl)
{
    const int s = blockIdx.x;
    const int t = threadIdx.x;
    __shared__ float cs[32], sn[32], kr[64];

    if (t < 32) {
        float pos = (float)pos_ids[s];
        double freq = exp(-log(10000.0) * (double)t / 32.0);
        float arg = pos * (float)freq;
        cs[t] = cosf(arg);
        sn[t] = sinf(arg);
    }
    __syncthreads();
    if (t < 32) {
        float x0 = kvd[(long)s * KVD_W + KVLR + 2 * t];
        float x1 = kvd[(long)s * KVD_W + KVLR + 2 * t + 1];
        kr[t]      = x0 * cs[t] - x1 * sn[t];
        kr[32 + t] = x1 * cs[t] + x0 * sn[t];
    }
    __syncthreads();

    for (int idx = t; idx < HEADS * QD; idx += 256) {
        int h = idx / QD, d = idx % QD;
        float qa, ka;
        if (d < NOPE) {
            qa = q[(long)s * QUP_N + h * QD + d];
            ka = kv[(long)s * KUP_N + h * (NOPE + VD) + d];
        } else {
            int k = d - NOPE;
            int kk = k & 31;
            float x0 = q[(long)s * QUP_N + h * QD + NOPE + 2 * kk];
            float x1 = q[(long)s * QUP_N + h * QD + NOPE + 2 * kk + 1];
            qa = (k < 32) ? (x0 * cs[kk] - x1 * sn[kk])
                          : (x1 * cs[kk] + x0 * sn[kk]);
            ka = kr[k];
        }
        long o = ((long)h * S_LEN + s) * QD + d;
        split1(qa, &qh[o], &ql[o]);
        split1(ka, &kh[o], &kl[o]);
    }
    for (int idx = t; idx < HEADS * VD; idx += 256) {
        int h = idx / VD, d = idx % VD;
        long o = ((long)h * VD + d) * S_LEN + s;
        split1(kv[(long)s * KUP_N + h * (NOPE + VD) + NOPE + d], &vh[o], &vl[o]);
    }
}

// ---------------------------------------------------------------------------
// Causal softmax: fp32 in-place (full zero fill) + bf16 hi/lo out (banded)
// ---------------------------------------------------------------------------
__global__ void softmax_causal(float* __restrict__ attn,
                               __nv_bfloat16* __restrict__ H,
                               __nv_bfloat16* __restrict__ L)
{
    const long row = blockIdx.x;
    const int i = (int)(row & (S_LEN - 1));
    float* p = attn + row * S_LEN;
    __nv_bfloat16* h = H + row * S_LEN;
    __nv_bfloat16* l = L + row * S_LEN;
    const int n = i + 1;
    const int band = ((i >> 7) + 1) << 7;   // next multiple of 128
    __shared__ float red[256];

    float mx = -INFINITY;
    for (int j = threadIdx.x; j < n; j += 256) mx = fmaxf(mx, p[j]);
    red[threadIdx.x] = mx;
    __syncthreads();
    for (int o = 128; o > 0; o >>= 1) {
        if (threadIdx.x < o)
            red[threadIdx.x] = fmaxf(red[threadIdx.x], red[threadIdx.x + o]);
        __syncthreads();
    }
    mx = red[0];
    __syncthreads();

    float s = 0.f;
    for (int j = threadIdx.x; j < n; j += 256) {
        float e = expf(p[j] - mx);
        p[j] = e;
        s += e;
    }
    red[threadIdx.x] = s;
    __syncthreads();
    for (int o = 128; o > 0; o >>= 1) {
        if (threadIdx.x < o) red[threadIdx.x] += red[threadIdx.x + o];
        __syncthreads();
    }
    float inv = 1.f / red[0];
    for (int j = threadIdx.x; j < n; j += 256) {
        float v = p[j] * inv;
        p[j] = v;
        split1(v, &h[j], &l[j]);
    }
    __nv_bfloat16 z = __float2bfloat16(0.f);
    for (int j = n + threadIdx.x; j < band; j += 256) { h[j] = z; l[j] = z; }
    for (int j = n + threadIdx.x; j < S_LEN; j += 256) p[j] = 0.f;
}

// ---------------------------------------------------------------------------
extern "C" void kernel_launch(void* const* d_in, const int* in_sizes, int n_in,
                              void* d_out, int out_size)
{
    (void)in_sizes; (void)n_in; (void)out_size;
    const float* hid  = (const float*)d_in[0];
    const int*   pos  = (const int*)  d_in[1];
    const float* Wqd  = (const float*)d_in[3];
    const float* bqd  = (const float*)d_in[4];
    const float* gq   = (const float*)d_in[5];
    const float* Wqu  = (const float*)d_in[6];
    const float* Wkd  = (const float*)d_in[7];
    const float* bkd  = (const float*)d_in[8];
    const float* gkv  = (const float*)d_in[9];
    const float* Wku  = (const float*)d_in[10];
    const float* Wo   = (const float*)d_in[11];

    float* out  = (float*)d_out;
    float* attn = out + (long)S_LEN * HID;

    void *pf = nullptr, *ph = nullptr, *pl = nullptr;
    cudaGetSymbolAddress(&pf, g_f32);
    cudaGetSymbolAddress(&ph, g_hi);
    cudaGetSymbolAddress(&pl, g_lo);
    float* F = (float*)pf;
    __nv_bfloat16* Hh = (__nv_bfloat16*)ph;
    __nv_bfloat16* Ll = (__nv_bfloat16*)pl;

    float* qraw = F + F_QRAW;
    float* qbuf = F + F_QBUF;
    float* kvd  = F + F_KVD;
    float* kv   = F + F_KV;
    float* ctx  = F + F_CTX;

    static bool attr_done = false;
    const int smem128 = (256 + 256) * SST * 2 * STAGES; // 122880
    const int smem64  = (256 + 128) * SST * 2 * STAGES; // 92160
    if (!attr_done) {
        cudaFuncSetAttribute(gemm_hl<128,false,false>,
            cudaFuncAttributeMaxDynamicSharedMemorySize, smem128);
        cudaFuncSetAttribute(gemm_hl<128,true,false>,
            cudaFuncAttributeMaxDynamicSharedMemorySize, smem128);
        cudaFuncSetAttribute(gemm_hl<128,false,true>,
            cudaFuncAttributeMaxDynamicSharedMemorySize, smem128);
        cudaFuncSetAttribute(gemm_hl<64,false,false>,
            cudaFuncAttributeMaxDynamicSharedMemorySize, smem64);
        attr_done = true;
    }

    const dim3 blk(256);
    const float qk_scale = 0.07216878364870323f;   // 1/sqrt(192)

    // 0. pre-split inputs
    split_hl<<<(unsigned)(((long)S_LEN*HID)/1024), blk>>>(hid, Hh+O_HID, Ll+O_HID, (long)S_LEN*HID);
    split_hl<<<(unsigned)(((long)QLR*HID)/1024), blk>>>(Wqd, Hh+O_WQD, Ll+O_WQD, (long)QLR*HID);
    split_hl<<<(unsigned)(((long)QUP_N*QLR)/1024), blk>>>(Wqu, Hh+O_WQU, Ll+O_WQU, (long)QUP_N*QLR);
    split_hl<<<(unsigned)(((long)KVD_W*HID)/1024), blk>>>(Wkd, Hh+O_WKD, Ll+O_WKD, (long)KVD_W*HID);
    split_hl<<<(unsigned)(((long)KUP_N*KVLR)/1024), blk>>>(Wku, Hh+O_WKU, Ll+O_WKU, (long)KUP_N*KVLR);
    split_hl<<<(unsigned)(((long)HID*HEADS*VD)/1024), blk>>>(Wo, Hh+O_WO, Ll+O_WO, (long)HID*HEADS*VD);

    // 1. qraw = hid @ Wq_down^T + bq
    gemm_hl<128,false,false><<<dim3(QLR/128, S_LEN/128, 1), blk, smem128>>>(
        Hh+O_HID, Ll+O_HID, 0, Hh+O_WQD, Ll+O_WQD, 0,
        qraw, 0, nullptr, nullptr, HID, HID, HID, QLR, bqd, 1.f);
    // 2. rmsnorm -> hi/lo
    rmsnorm_split<<<S_LEN, blk>>>(qraw, gq, Hh+O_QRN, Ll+O_QRN, QLR, QLR);
    // 3. q = qrn @ Wq_up^T
    gemm_hl<128,false,false><<<dim3(QUP_N/128, S_LEN/128, 1), blk, smem128>>>(
        Hh+O_QRN, Ll+O_QRN, 0, Hh+O_WQU, Ll+O_WQU, 0,
        qbuf, 0, nullptr, nullptr, QLR, QLR, QLR, QUP_N, nullptr, 1.f);
    // 4. kvd = hid @ Wkv_down^T + bkv  (N=576 -> BN=64)
    gemm_hl<64,false,false><<<dim3(KVD_W/64, S_LEN/128, 1), blk, smem64>>>(
        Hh+O_HID, Ll+O_HID, 0, Hh+O_WKD, Ll+O_WKD, 0,
        kvd, 0, nullptr, nullptr, HID, HID, HID, KVD_W, bkd, 1.f);
    // 5. rmsnorm first 512 cols -> hi/lo
    rmsnorm_split<<<S_LEN, blk>>>(kvd, gkv, Hh+O_KVN, Ll+O_KVN, KVLR, KVD_W);
    // 6. kv = kvn @ Wkv_up^T
    gemm_hl<128,false,false><<<dim3(KUP_N/128, S_LEN/128, 1), blk, smem128>>>(
        Hh+O_KVN, Ll+O_KVN, 0, Hh+O_WKU, Ll+O_WKU, 0,
        kv, 0, nullptr, nullptr, KVLR, KVLR, KVLR, KUP_N, nullptr, 1.f);
    // 7. assemble + rope -> hi/lo
    assemble_rope<<<S_LEN, blk>>>(qbuf, kvd, kv, pos,
        Hh+O_QALL, Ll+O_QALL, Hh+O_KALL, Ll+O_KALL, Hh+O_VT, Ll+O_VT);
    // 8. scores -> attn fp32 (causal block skip)
    gemm_hl<128,true,false><<<dim3(S_LEN/128, S_LEN/128, HEADS), blk, smem128>>>(
        Hh+O_QALL, Ll+O_QALL, (long)S_LEN*QD,
        Hh+O_KALL, Ll+O_KALL, (long)S_LEN*QD,
        attn, (long)S_LEN*S_LEN, nullptr, nullptr,
        QD, QD, QD, S_LEN, nullptr, qk_scale);
    // 9. causal softmax -> fp32 + hi/lo
    softmax_causal<<<HEADS * S_LEN, blk>>>(attn, Hh+O_ATTN, Ll+O_ATTN);
    // 10. ctx = attn @ v (K clamped); epilogue also emits hi/lo ctx
    gemm_hl<128,false,true><<<dim3(1, S_LEN/128, HEADS), blk, smem128>>>(
        Hh+O_ATTN, Ll+O_ATTN, (long)S_LEN*S_LEN,
        Hh+O_VT, Ll+O_VT, (long)VD*S_LEN,
        ctx, (long)VD, Hh+O_CTX, Ll+O_CTX,
        S_LEN, S_LEN, S_LEN, HID, nullptr, 1.f);
    // 11. out = ctx @ Wo^T
    gemm_hl<128,false,false><<<dim3(HID/128, S_LEN/128, 1), blk, smem128>>>(
        Hh+O_CTX, Ll+O_CTX, 0, Hh+O_WO, Ll+O_WO, 0,
        out, 0, nullptr, nullptr, HID, HID, HID, HID, nullptr, 1.f);
}